// round 13
// baseline (speedup 1.0000x reference)
#include <cuda_runtime.h>
#include <math_constants.h>

#define BATCH   32
#define SEQ     8192
#define HID     256
#define NSPLIT  128
#define CHUNK   (SEQ / NSPLIT)        // 64
#define WARPS   8
#define ROWS_PER_IT (WARPS * 2)       // 16 rows per block-iteration
#define ITERS   (CHUNK / ROWS_PER_IT) // 4
#define FIN_Y   8                     // tail blocks per batch

// Scratch (allocation-free rule: __device__ globals)
__device__ float g_pm[BATCH * NSPLIT];
__device__ float g_pl[BATCH * NSPLIT];
__device__ float g_pctx[BATCH * NSPLIT * HID];

// Kernel 1: fused score + online softmax + context partials.
// grid (BATCH, NSPLIT), block 256.  (unchanged; measured ~42us)
__global__ __launch_bounds__(256, 4) void attn_pass1(
    const float* __restrict__ dec,   // (B, H)
    const float* __restrict__ enc,   // (B, S, H)
    float* __restrict__ score_out)   // (B, S) raw scores (normalized later)
{
    const int b     = blockIdx.x;
    const int chunk = blockIdx.y;
    const int tid   = threadIdx.x;
    const int wid   = tid >> 5;
    const int lane  = tid & 31;

    __shared__ float sdec[HID];
    __shared__ float sm[WARPS];
    __shared__ float sl[WARPS];
    __shared__ float sctx[WARPS][HID];

    sdec[tid] = dec[b * HID + tid];
    __syncthreads();

    const float4 d0 = *(const float4*)&sdec[lane * 4];
    const float4 d1 = *(const float4*)&sdec[128 + lane * 4];

    const float* encb = enc + (size_t)b * SEQ * HID + (size_t)chunk * CHUNK * HID;

    float m = -CUDART_INF_F;
    float l = 0.f;
    float c0x = 0.f, c0y = 0.f, c0z = 0.f, c0w = 0.f;
    float c1x = 0.f, c1y = 0.f, c1z = 0.f, c1w = 0.f;

    // prefetch rows for iteration 0: rows (2*wid, 2*wid+1)
    const float* r0 = encb + (size_t)(2 * wid) * HID;
    float4 pA0 = *(const float4*)&r0[lane * 4];
    float4 pA1 = *(const float4*)&r0[128 + lane * 4];
    float4 pB0 = *(const float4*)&r0[HID + lane * 4];
    float4 pB1 = *(const float4*)&r0[HID + 128 + lane * 4];

    #pragma unroll
    for (int it = 0; it < ITERS; ++it) {
        const int s0 = 2 * wid + it * ROWS_PER_IT;   // first of the row pair
        const float4 a0 = pA0, a1 = pA1;             // row s0
        const float4 b0 = pB0, b1 = pB1;             // row s0+1

        if (it + 1 < ITERS) {
            const float* nrow = encb + (size_t)(s0 + ROWS_PER_IT) * HID;
            pA0 = *(const float4*)&nrow[lane * 4];
            pA1 = *(const float4*)&nrow[128 + lane * 4];
            pB0 = *(const float4*)&nrow[HID + lane * 4];
            pB1 = *(const float4*)&nrow[HID + 128 + lane * 4];
        }

        // two independent dot products
        float pa = a0.x * d0.x + a0.y * d0.y + a0.z * d0.z + a0.w * d0.w
                 + a1.x * d1.x + a1.y * d1.y + a1.z * d1.z + a1.w * d1.w;
        float pb = b0.x * d0.x + b0.y * d0.y + b0.z * d0.z + b0.w * d0.w
                 + b1.x * d1.x + b1.y * d1.y + b1.z * d1.z + b1.w * d1.w;

        // merged reduction: after the xor-16 step, lower half-warp carries pa,
        // upper half-warp carries pb; 4 butterfly steps finish both at once.
        pa += __shfl_xor_sync(0xffffffffu, pa, 16);
        pb += __shfl_xor_sync(0xffffffffu, pb, 16);
        float t = (lane & 16) ? pb : pa;
        #pragma unroll
        for (int o = 8; o; o >>= 1) t += __shfl_xor_sync(0xffffffffu, t, o);
        const float scoreA = __shfl_sync(0xffffffffu, t, 0);
        const float scoreB = __shfl_sync(0xffffffffu, t, 16);

        if (lane == 0) {
            float2 sc = make_float2(scoreA, scoreB);
            *(float2*)&score_out[(size_t)b * SEQ + (size_t)chunk * CHUNK + s0] = sc;
        }

        // online-softmax update with both rows folded in at once
        const float mn = fmaxf(m, fmaxf(scoreA, scoreB));
        const float alpha = __expf(m - mn);
        const float wA    = __expf(scoreA - mn);
        const float wB    = __expf(scoreB - mn);
        l = l * alpha + wA + wB;
        c0x = c0x * alpha + wA * a0.x + wB * b0.x;
        c0y = c0y * alpha + wA * a0.y + wB * b0.y;
        c0z = c0z * alpha + wA * a0.z + wB * b0.z;
        c0w = c0w * alpha + wA * a0.w + wB * b0.w;
        c1x = c1x * alpha + wA * a1.x + wB * b1.x;
        c1y = c1y * alpha + wA * a1.y + wB * b1.y;
        c1z = c1z * alpha + wA * a1.z + wB * b1.z;
        c1w = c1w * alpha + wA * a1.w + wB * b1.w;
        m = mn;
    }

    if (lane == 0) { sm[wid] = m; sl[wid] = l; }
    sctx[wid][lane * 4 + 0] = c0x;  sctx[wid][lane * 4 + 1] = c0y;
    sctx[wid][lane * 4 + 2] = c0z;  sctx[wid][lane * 4 + 3] = c0w;
    sctx[wid][128 + lane * 4 + 0] = c1x;  sctx[wid][128 + lane * 4 + 1] = c1y;
    sctx[wid][128 + lane * 4 + 2] = c1z;  sctx[wid][128 + lane * 4 + 3] = c1w;
    __syncthreads();

    // combine 8 warp partials; each thread owns one h = tid
    float M = sm[0];
    #pragma unroll
    for (int w2 = 1; w2 < WARPS; ++w2) M = fmaxf(M, sm[w2]);
    float L = 0.f, acc = 0.f;
    #pragma unroll
    for (int w2 = 0; w2 < WARPS; ++w2) {
        const float f = __expf(sm[w2] - M);
        L   += f * sl[w2];
        acc += f * sctx[w2][tid];
    }
    const int pidx = b * NSPLIT + chunk;
    if (tid == 0) { g_pm[pidx] = M; g_pl[pidx] = L; }
    g_pctx[(size_t)pidx * HID + tid] = acc;
}

// Kernel 2: finish — grid (BATCH, FIN_Y), block 256.
// Parallel (M,L) reduce; every block normalizes a 1024-score slice.
// y==0 blocks compute context with 2D (kgroup x h-float4) parallelism:
// each thread walks only 32 chunks with 8-deep float4 staging.
__global__ __launch_bounds__(256) void attn_finish(
    float* __restrict__ prob,        // (B, S) raw scores in, probs out
    float* __restrict__ ctx_out)     // (B, H)
{
    const int b    = blockIdx.x;
    const int y    = blockIdx.y;
    const int tid  = threadIdx.x;
    const int lane = tid & 31;

    __shared__ float  sf[NSPLIT];    // expf(pm[k]-M), k = 0..127
    __shared__ float  sredm[4];      // per-warp maxes
    __shared__ float  sredl[4];      // per-warp L partials
    __shared__ float  sML;           // inv_l
    __shared__ float4 spart[4][HID / 4];  // per-kgroup context partials (4 KB)

    // issue the prob float4 load EARLY so it overlaps the (M,L) reduction
    float4* p = (float4*)(prob + (size_t)b * SEQ + (size_t)y * (SEQ / FIN_Y));
    float4 v = p[tid];

    // ---- parallel (M, L): threads 0..127, one chunk each ----
    if (tid < NSPLIT) {
        float mx = g_pm[b * NSPLIT + tid];
        #pragma unroll
        for (int o = 16; o; o >>= 1) mx = fmaxf(mx, __shfl_xor_sync(0xffffffffu, mx, o));
        if (lane == 0) sredm[tid >> 5] = mx;
    }
    __syncthreads();
    const float M = fmaxf(fmaxf(sredm[0], sredm[1]), fmaxf(sredm[2], sredm[3]));

    if (tid < NSPLIT) {
        const float f = __expf(g_pm[b * NSPLIT + tid] - M);
        sf[tid] = f;
        float fl = f * g_pl[b * NSPLIT + tid];
        #pragma unroll
        for (int o = 16; o; o >>= 1) fl += __shfl_xor_sync(0xffffffffu, fl, o);
        if (lane == 0) sredl[tid >> 5] = fl;
    }
    __syncthreads();
    if (tid == 0)
        sML = __frcp_rn(sredl[0] + sredl[1] + sredl[2] + sredl[3]);
    __syncthreads();
    const float inv_l = sML;

    // ---- normalize this block's 1024-score slice ----
    v.x = __expf(v.x - M) * inv_l;
    v.y = __expf(v.y - M) * inv_l;
    v.z = __expf(v.z - M) * inv_l;
    v.w = __expf(v.w - M) * inv_l;
    p[tid] = v;

    // ---- context combine (y == 0): 2D threads = (kgroup 0..3, h4 0..63) ----
    if (y == 0) {
        const int h4 = (tid & 63);           // float4 column: h = h4*4 .. h4*4+3
        const int kg = tid >> 6;             // kgroup: chunks kg*32 .. kg*32+31
        const float4* base = (const float4*)
            &g_pctx[(size_t)(b * NSPLIT + kg * 32) * HID + h4 * 4];
        // stride between consecutive chunks, in float4 units
        const int stride4 = HID / 4;         // 64

        float4 acc = make_float4(0.f, 0.f, 0.f, 0.f);
        #pragma unroll
        for (int g = 0; g < 4; ++g) {        // 32 chunks = 4 groups of 8 staged
            float4 vals[8];
            #pragma unroll
            for (int j = 0; j < 8; ++j)
                vals[j] = base[(g * 8 + j) * stride4];   // 8 LDG.128 in flight
            #pragma unroll
            for (int j = 0; j < 8; ++j) {
                const float f = sf[kg * 32 + g * 8 + j];
                acc.x += f * vals[j].x;
                acc.y += f * vals[j].y;
                acc.z += f * vals[j].z;
                acc.w += f * vals[j].w;
            }
        }
        spart[kg][h4] = acc;
    }
    __syncthreads();

    if (y == 0 && tid < HID / 4) {
        float4 a0 = spart[0][tid], a1 = spart[1][tid];
        float4 a2 = spart[2][tid], a3 = spart[3][tid];
        float4 r;
        r.x = (a0.x + a1.x + a2.x + a3.x) * inv_l;
        r.y = (a0.y + a1.y + a2.y + a3.y) * inv_l;
        r.z = (a0.z + a1.z + a2.z + a3.z) * inv_l;
        r.w = (a0.w + a1.w + a2.w + a3.w) * inv_l;
        ((float4*)(ctx_out + b * HID))[tid] = r;
    }
}

extern "C" void kernel_launch(void* const* d_in, const int* in_sizes, int n_in,
                              void* d_out, int out_size)
{
    const float* dec = (const float*)d_in[0];
    const float* enc = (const float*)d_in[1];
    if (n_in >= 2 && in_sizes[0] > in_sizes[1]) {  // defensive: dec is the small one
        const float* t = dec; dec = enc; enc = t;
    }

    float* out       = (float*)d_out;
    float* prob_out  = out;                       // (B, S)
    float* ctx_out   = out + (size_t)BATCH * SEQ; // (B, H)

    dim3 g1(BATCH, NSPLIT);
    attn_pass1<<<g1, 256>>>(dec, enc, prob_out);
    dim3 g2(BATCH, FIN_Y);
    attn_finish<<<g2, 256>>>(prob_out, ctx_out);
}

// round 14
// speedup vs baseline: 1.0485x; 1.0485x over previous
#include <cuda_runtime.h>
#include <math_constants.h>

#define BATCH   32
#define SEQ     8192
#define HID     256
#define NSPLIT  128
#define CHUNK   (SEQ / NSPLIT)        // 64
#define WARPS   8
#define ROWS_PER_IT (WARPS * 2)       // 16 rows per block-iteration
#define ITERS   (CHUNK / ROWS_PER_IT) // 4
#define FIN_Y   8                     // tail blocks per batch

// Scratch (allocation-free rule: __device__ globals)
__device__ float g_pm[BATCH * NSPLIT];
__device__ float g_pl[BATCH * NSPLIT];
__device__ float g_pctx[BATCH * NSPLIT * HID];

// Kernel 1: fused score + online softmax + context partials.
// grid (BATCH, NSPLIT), block 256.  (unchanged; measured ~42us)
__global__ __launch_bounds__(256, 4) void attn_pass1(
    const float* __restrict__ dec,   // (B, H)
    const float* __restrict__ enc,   // (B, S, H)
    float* __restrict__ score_out)   // (B, S) raw scores (normalized later)
{
    const int b     = blockIdx.x;
    const int chunk = blockIdx.y;
    const int tid   = threadIdx.x;
    const int wid   = tid >> 5;
    const int lane  = tid & 31;

    __shared__ float sdec[HID];
    __shared__ float sm[WARPS];
    __shared__ float sl[WARPS];
    __shared__ float sctx[WARPS][HID];

    sdec[tid] = dec[b * HID + tid];
    __syncthreads();

    const float4 d0 = *(const float4*)&sdec[lane * 4];
    const float4 d1 = *(const float4*)&sdec[128 + lane * 4];

    const float* encb = enc + (size_t)b * SEQ * HID + (size_t)chunk * CHUNK * HID;

    float m = -CUDART_INF_F;
    float l = 0.f;
    float c0x = 0.f, c0y = 0.f, c0z = 0.f, c0w = 0.f;
    float c1x = 0.f, c1y = 0.f, c1z = 0.f, c1w = 0.f;

    // prefetch rows for iteration 0: rows (2*wid, 2*wid+1)
    const float* r0 = encb + (size_t)(2 * wid) * HID;
    float4 pA0 = *(const float4*)&r0[lane * 4];
    float4 pA1 = *(const float4*)&r0[128 + lane * 4];
    float4 pB0 = *(const float4*)&r0[HID + lane * 4];
    float4 pB1 = *(const float4*)&r0[HID + 128 + lane * 4];

    #pragma unroll
    for (int it = 0; it < ITERS; ++it) {
        const int s0 = 2 * wid + it * ROWS_PER_IT;   // first of the row pair
        const float4 a0 = pA0, a1 = pA1;             // row s0
        const float4 b0 = pB0, b1 = pB1;             // row s0+1

        if (it + 1 < ITERS) {
            const float* nrow = encb + (size_t)(s0 + ROWS_PER_IT) * HID;
            pA0 = *(const float4*)&nrow[lane * 4];
            pA1 = *(const float4*)&nrow[128 + lane * 4];
            pB0 = *(const float4*)&nrow[HID + lane * 4];
            pB1 = *(const float4*)&nrow[HID + 128 + lane * 4];
        }

        // two independent dot products
        float pa = a0.x * d0.x + a0.y * d0.y + a0.z * d0.z + a0.w * d0.w
                 + a1.x * d1.x + a1.y * d1.y + a1.z * d1.z + a1.w * d1.w;
        float pb = b0.x * d0.x + b0.y * d0.y + b0.z * d0.z + b0.w * d0.w
                 + b1.x * d1.x + b1.y * d1.y + b1.z * d1.z + b1.w * d1.w;

        // merged reduction: after the xor-16 step, lower half-warp carries pa,
        // upper half-warp carries pb; 4 butterfly steps finish both at once.
        pa += __shfl_xor_sync(0xffffffffu, pa, 16);
        pb += __shfl_xor_sync(0xffffffffu, pb, 16);
        float t = (lane & 16) ? pb : pa;
        #pragma unroll
        for (int o = 8; o; o >>= 1) t += __shfl_xor_sync(0xffffffffu, t, o);
        const float scoreA = __shfl_sync(0xffffffffu, t, 0);
        const float scoreB = __shfl_sync(0xffffffffu, t, 16);

        if (lane == 0) {
            float2 sc = make_float2(scoreA, scoreB);
            *(float2*)&score_out[(size_t)b * SEQ + (size_t)chunk * CHUNK + s0] = sc;
        }

        // online-softmax update with both rows folded in at once
        const float mn = fmaxf(m, fmaxf(scoreA, scoreB));
        const float alpha = __expf(m - mn);
        const float wA    = __expf(scoreA - mn);
        const float wB    = __expf(scoreB - mn);
        l = l * alpha + wA + wB;
        c0x = c0x * alpha + wA * a0.x + wB * b0.x;
        c0y = c0y * alpha + wA * a0.y + wB * b0.y;
        c0z = c0z * alpha + wA * a0.z + wB * b0.z;
        c0w = c0w * alpha + wA * a0.w + wB * b0.w;
        c1x = c1x * alpha + wA * a1.x + wB * b1.x;
        c1y = c1y * alpha + wA * a1.y + wB * b1.y;
        c1z = c1z * alpha + wA * a1.z + wB * b1.z;
        c1w = c1w * alpha + wA * a1.w + wB * b1.w;
        m = mn;
    }

    if (lane == 0) { sm[wid] = m; sl[wid] = l; }
    sctx[wid][lane * 4 + 0] = c0x;  sctx[wid][lane * 4 + 1] = c0y;
    sctx[wid][lane * 4 + 2] = c0z;  sctx[wid][lane * 4 + 3] = c0w;
    sctx[wid][128 + lane * 4 + 0] = c1x;  sctx[wid][128 + lane * 4 + 1] = c1y;
    sctx[wid][128 + lane * 4 + 2] = c1z;  sctx[wid][128 + lane * 4 + 3] = c1w;
    __syncthreads();

    // combine 8 warp partials; each thread owns one h = tid
    float M = sm[0];
    #pragma unroll
    for (int w2 = 1; w2 < WARPS; ++w2) M = fmaxf(M, sm[w2]);
    float L = 0.f, acc = 0.f;
    #pragma unroll
    for (int w2 = 0; w2 < WARPS; ++w2) {
        const float f = __expf(sm[w2] - M);
        L   += f * sl[w2];
        acc += f * sctx[w2][tid];
    }
    const int pidx = b * NSPLIT + chunk;
    if (tid == 0) { g_pm[pidx] = M; g_pl[pidx] = L; }
    g_pctx[(size_t)pidx * HID + tid] = acc;
}

// Kernel 2: finish — grid (BATCH, FIN_Y), block 256.
// All loads (prob slice + 4 pctx float4 per thread) are issued at entry and
// overlap the parallel (M,L) reduction. Context combine spread over ALL
// blocks: block (b,y) owns h-slice [y*32, y*32+32); warp c handles float4
// column y*8+c; lanes = chunks; in-warp float4 butterfly; lane0 stores.
__global__ __launch_bounds__(256) void attn_finish(
    float* __restrict__ prob,        // (B, S) raw scores in, probs out
    float* __restrict__ ctx_out)     // (B, H)
{
    const int b    = blockIdx.x;
    const int y    = blockIdx.y;
    const int tid  = threadIdx.x;
    const int lane = tid & 31;
    const int c    = tid >> 5;       // warp id = float4 column within slice
    const int k    = lane;           // chunk lane

    __shared__ float sf[NSPLIT];     // expf(pm[k]-M), k = 0..127
    __shared__ float sredm[4];
    __shared__ float sredl[4];
    __shared__ float sML;            // inv_l

    // ---- issue ALL global loads up front (overlap the reductions) ----
    float4* p = (float4*)(prob + (size_t)b * SEQ + (size_t)y * (SEQ / FIN_Y));
    float4 v = p[tid];

    // pctx loads: column (y*8 + c), chunks k, k+32, k+64, k+96
    const float4* pc = (const float4*)g_pctx
                     + (size_t)(b * NSPLIT) * (HID / 4) + (y * 8 + c);
    const int cs = HID / 4;          // chunk stride in float4 units (64)
    const float4 u0 = pc[(size_t)(k)      * cs];
    const float4 u1 = pc[(size_t)(k + 32) * cs];
    const float4 u2 = pc[(size_t)(k + 64) * cs];
    const float4 u3 = pc[(size_t)(k + 96) * cs];

    // ---- parallel (M, L): threads 0..127, one chunk each ----
    if (tid < NSPLIT) {
        float mx = g_pm[b * NSPLIT + tid];
        #pragma unroll
        for (int o = 16; o; o >>= 1) mx = fmaxf(mx, __shfl_xor_sync(0xffffffffu, mx, o));
        if (lane == 0) sredm[tid >> 5] = mx;
    }
    __syncthreads();
    const float M = fmaxf(fmaxf(sredm[0], sredm[1]), fmaxf(sredm[2], sredm[3]));

    if (tid < NSPLIT) {
        const float f = __expf(g_pm[b * NSPLIT + tid] - M);
        sf[tid] = f;
        float fl = f * g_pl[b * NSPLIT + tid];
        #pragma unroll
        for (int o = 16; o; o >>= 1) fl += __shfl_xor_sync(0xffffffffu, fl, o);
        if (lane == 0) sredl[tid >> 5] = fl;
    }
    __syncthreads();
    if (tid == 0)
        sML = __frcp_rn(sredl[0] + sredl[1] + sredl[2] + sredl[3]);
    __syncthreads();
    const float inv_l = sML;

    // ---- normalize this block's 1024-score slice ----
    v.x = __expf(v.x - M) * inv_l;
    v.y = __expf(v.y - M) * inv_l;
    v.z = __expf(v.z - M) * inv_l;
    v.w = __expf(v.w - M) * inv_l;
    p[tid] = v;

    // ---- context combine: weight the 4 preloaded values, warp-reduce ----
    const float f0 = sf[k], f1 = sf[k + 32], f2 = sf[k + 64], f3 = sf[k + 96];
    float ax = f0 * u0.x + f1 * u1.x + f2 * u2.x + f3 * u3.x;
    float ay = f0 * u0.y + f1 * u1.y + f2 * u2.y + f3 * u3.y;
    float az = f0 * u0.z + f1 * u1.z + f2 * u2.z + f3 * u3.z;
    float aw = f0 * u0.w + f1 * u1.w + f2 * u2.w + f3 * u3.w;
    #pragma unroll
    for (int o = 16; o; o >>= 1) {
        ax += __shfl_xor_sync(0xffffffffu, ax, o);
        ay += __shfl_xor_sync(0xffffffffu, ay, o);
        az += __shfl_xor_sync(0xffffffffu, az, o);
        aw += __shfl_xor_sync(0xffffffffu, aw, o);
    }
    if (lane == 0) {
        float4 r = make_float4(ax * inv_l, ay * inv_l, az * inv_l, aw * inv_l);
        ((float4*)(ctx_out + b * HID))[y * 8 + c] = r;
    }
}

extern "C" void kernel_launch(void* const* d_in, const int* in_sizes, int n_in,
                              void* d_out, int out_size)
{
    const float* dec = (const float*)d_in[0];
    const float* enc = (const float*)d_in[1];
    if (n_in >= 2 && in_sizes[0] > in_sizes[1]) {  // defensive: dec is the small one
        const float* t = dec; dec = enc; enc = t;
    }

    float* out       = (float*)d_out;
    float* prob_out  = out;                       // (B, S)
    float* ctx_out   = out + (size_t)BATCH * SEQ; // (B, H)

    dim3 g1(BATCH, NSPLIT);
    attn_pass1<<<g1, 256>>>(dec, enc, prob_out);
    dim3 g2(BATCH, FIN_Y);
    attn_finish<<<g2, 256>>>(prob_out, ctx_out);
}

// round 15
// speedup vs baseline: 1.0804x; 1.0305x over previous
#include <cuda_runtime.h>
#include <math_constants.h>

#define BATCH   32
#define SEQ     8192
#define HID     256
#define NSPLIT  128
#define CHUNK   (SEQ / NSPLIT)        // 64
#define WARPS   8
#define ROWS_PER_IT (WARPS * 2)       // 16 rows per block-iteration
#define ITERS   (CHUNK / ROWS_PER_IT) // 4
#define FIN_Y   8                     // tail blocks per batch

// Scratch (allocation-free rule: __device__ globals)
__device__ float g_pm[BATCH * NSPLIT];
__device__ float g_pl[BATCH * NSPLIT];
__device__ float g_pctx[BATCH * NSPLIT * HID];

// Kernel 1: fused score + online softmax + context partials.
// grid (BATCH, NSPLIT), block 256.  (unchanged; measured ~42-43us)
__global__ __launch_bounds__(256, 4) void attn_pass1(
    const float* __restrict__ dec,   // (B, H)
    const float* __restrict__ enc,   // (B, S, H)
    float* __restrict__ score_out)   // (B, S) raw scores (normalized later)
{
    const int b     = blockIdx.x;
    const int chunk = blockIdx.y;
    const int tid   = threadIdx.x;
    const int wid   = tid >> 5;
    const int lane  = tid & 31;

    __shared__ float sdec[HID];
    __shared__ float sm[WARPS];
    __shared__ float sl[WARPS];
    __shared__ float sctx[WARPS][HID];

    sdec[tid] = dec[b * HID + tid];
    __syncthreads();

    const float4 d0 = *(const float4*)&sdec[lane * 4];
    const float4 d1 = *(const float4*)&sdec[128 + lane * 4];

    const float* encb = enc + (size_t)b * SEQ * HID + (size_t)chunk * CHUNK * HID;

    float m = -CUDART_INF_F;
    float l = 0.f;
    float c0x = 0.f, c0y = 0.f, c0z = 0.f, c0w = 0.f;
    float c1x = 0.f, c1y = 0.f, c1z = 0.f, c1w = 0.f;

    // prefetch rows for iteration 0: rows (2*wid, 2*wid+1)
    const float* r0 = encb + (size_t)(2 * wid) * HID;
    float4 pA0 = *(const float4*)&r0[lane * 4];
    float4 pA1 = *(const float4*)&r0[128 + lane * 4];
    float4 pB0 = *(const float4*)&r0[HID + lane * 4];
    float4 pB1 = *(const float4*)&r0[HID + 128 + lane * 4];

    #pragma unroll
    for (int it = 0; it < ITERS; ++it) {
        const int s0 = 2 * wid + it * ROWS_PER_IT;   // first of the row pair
        const float4 a0 = pA0, a1 = pA1;             // row s0
        const float4 b0 = pB0, b1 = pB1;             // row s0+1

        if (it + 1 < ITERS) {
            const float* nrow = encb + (size_t)(s0 + ROWS_PER_IT) * HID;
            pA0 = *(const float4*)&nrow[lane * 4];
            pA1 = *(const float4*)&nrow[128 + lane * 4];
            pB0 = *(const float4*)&nrow[HID + lane * 4];
            pB1 = *(const float4*)&nrow[HID + 128 + lane * 4];
        }

        // two independent dot products
        float pa = a0.x * d0.x + a0.y * d0.y + a0.z * d0.z + a0.w * d0.w
                 + a1.x * d1.x + a1.y * d1.y + a1.z * d1.z + a1.w * d1.w;
        float pb = b0.x * d0.x + b0.y * d0.y + b0.z * d0.z + b0.w * d0.w
                 + b1.x * d1.x + b1.y * d1.y + b1.z * d1.z + b1.w * d1.w;

        // merged reduction: after the xor-16 step, lower half-warp carries pa,
        // upper half-warp carries pb; 4 butterfly steps finish both at once.
        pa += __shfl_xor_sync(0xffffffffu, pa, 16);
        pb += __shfl_xor_sync(0xffffffffu, pb, 16);
        float t = (lane & 16) ? pb : pa;
        #pragma unroll
        for (int o = 8; o; o >>= 1) t += __shfl_xor_sync(0xffffffffu, t, o);
        const float scoreA = __shfl_sync(0xffffffffu, t, 0);
        const float scoreB = __shfl_sync(0xffffffffu, t, 16);

        if (lane == 0) {
            float2 sc = make_float2(scoreA, scoreB);
            *(float2*)&score_out[(size_t)b * SEQ + (size_t)chunk * CHUNK + s0] = sc;
        }

        // online-softmax update with both rows folded in at once
        const float mn = fmaxf(m, fmaxf(scoreA, scoreB));
        const float alpha = __expf(m - mn);
        const float wA    = __expf(scoreA - mn);
        const float wB    = __expf(scoreB - mn);
        l = l * alpha + wA + wB;
        c0x = c0x * alpha + wA * a0.x + wB * b0.x;
        c0y = c0y * alpha + wA * a0.y + wB * b0.y;
        c0z = c0z * alpha + wA * a0.z + wB * b0.z;
        c0w = c0w * alpha + wA * a0.w + wB * b0.w;
        c1x = c1x * alpha + wA * a1.x + wB * b1.x;
        c1y = c1y * alpha + wA * a1.y + wB * b1.y;
        c1z = c1z * alpha + wA * a1.z + wB * b1.z;
        c1w = c1w * alpha + wA * a1.w + wB * b1.w;
        m = mn;
    }

    if (lane == 0) { sm[wid] = m; sl[wid] = l; }
    sctx[wid][lane * 4 + 0] = c0x;  sctx[wid][lane * 4 + 1] = c0y;
    sctx[wid][lane * 4 + 2] = c0z;  sctx[wid][lane * 4 + 3] = c0w;
    sctx[wid][128 + lane * 4 + 0] = c1x;  sctx[wid][128 + lane * 4 + 1] = c1y;
    sctx[wid][128 + lane * 4 + 2] = c1z;  sctx[wid][128 + lane * 4 + 3] = c1w;
    __syncthreads();

    // combine 8 warp partials; each thread owns one h = tid
    float M = sm[0];
    #pragma unroll
    for (int w2 = 1; w2 < WARPS; ++w2) M = fmaxf(M, sm[w2]);
    float L = 0.f, acc = 0.f;
    #pragma unroll
    for (int w2 = 0; w2 < WARPS; ++w2) {
        const float f = __expf(sm[w2] - M);
        L   += f * sl[w2];
        acc += f * sctx[w2][tid];
    }
    const int pidx = b * NSPLIT + chunk;
    if (tid == 0) { g_pm[pidx] = M; g_pl[pidx] = L; }
    g_pctx[(size_t)pidx * HID + tid] = acc;
}

// Kernel 2: finish — grid (BATCH, FIN_Y), block 256.
// Coalesced entry loads: col = tid&7 walks h (contiguous 128B per 8 lanes),
// ck = tid>>3 covers chunks {ck, ck+32, ck+64, ck+96}. Each warp LDG.128
// touches 4 lines (was 32). Reduction over chunks: in-warp xor-8/16
// butterfly -> per-warp partial in smem -> warp 0 finishes.
__global__ __launch_bounds__(256) void attn_finish(
    float* __restrict__ prob,        // (B, S) raw scores in, probs out
    float* __restrict__ ctx_out)     // (B, H)
{
    const int b    = blockIdx.x;
    const int y    = blockIdx.y;
    const int tid  = threadIdx.x;
    const int lane = tid & 31;
    const int wid  = tid >> 5;
    const int col  = tid & 7;        // float4 column within slice (h4 = y*8+col)
    const int ck   = tid >> 3;       // chunk base 0..31

    __shared__ float  sf[NSPLIT];    // expf(pm[k]-M)
    __shared__ float  sredm[4];
    __shared__ float  sredl[4];
    __shared__ float  sML;           // inv_l
    __shared__ float4 swacc[WARPS][8];  // per-warp column partials

    // ---- issue ALL global loads up front (overlap the reductions) ----
    float4* p = (float4*)(prob + (size_t)b * SEQ + (size_t)y * (SEQ / FIN_Y));
    float4 v = p[tid];

    const float4* pc = (const float4*)g_pctx
                     + (size_t)(b * NSPLIT) * (HID / 4) + (y * 8 + col);
    const int cs = HID / 4;          // chunk stride in float4 units (64)
    const float4 u0 = pc[(size_t)(ck)      * cs];
    const float4 u1 = pc[(size_t)(ck + 32) * cs];
    const float4 u2 = pc[(size_t)(ck + 64) * cs];
    const float4 u3 = pc[(size_t)(ck + 96) * cs];

    // ---- parallel (M, L): threads 0..127, one chunk each ----
    if (tid < NSPLIT) {
        float mx = g_pm[b * NSPLIT + tid];
        #pragma unroll
        for (int o = 16; o; o >>= 1) mx = fmaxf(mx, __shfl_xor_sync(0xffffffffu, mx, o));
        if (lane == 0) sredm[tid >> 5] = mx;
    }
    __syncthreads();
    const float M = fmaxf(fmaxf(sredm[0], sredm[1]), fmaxf(sredm[2], sredm[3]));

    if (tid < NSPLIT) {
        const float f = __expf(g_pm[b * NSPLIT + tid] - M);
        sf[tid] = f;
        float fl = f * g_pl[b * NSPLIT + tid];
        #pragma unroll
        for (int o = 16; o; o >>= 1) fl += __shfl_xor_sync(0xffffffffu, fl, o);
        if (lane == 0) sredl[tid >> 5] = fl;
    }
    __syncthreads();
    if (tid == 0)
        sML = __frcp_rn(sredl[0] + sredl[1] + sredl[2] + sredl[3]);
    __syncthreads();
    const float inv_l = sML;

    // ---- normalize this block's 1024-score slice ----
    v.x = __expf(v.x - M) * inv_l;
    v.y = __expf(v.y - M) * inv_l;
    v.z = __expf(v.z - M) * inv_l;
    v.w = __expf(v.w - M) * inv_l;
    p[tid] = v;

    // ---- context combine: weight preloaded values, reduce over chunks ----
    const float f0 = sf[ck], f1 = sf[ck + 32], f2 = sf[ck + 64], f3 = sf[ck + 96];
    float ax = f0 * u0.x + f1 * u1.x + f2 * u2.x + f3 * u3.x;
    float ay = f0 * u0.y + f1 * u1.y + f2 * u2.y + f3 * u3.y;
    float az = f0 * u0.z + f1 * u1.z + f2 * u2.z + f3 * u3.z;
    float aw = f0 * u0.w + f1 * u1.w + f2 * u2.w + f3 * u3.w;

    // lanes sharing a column are 8 apart: xor-8 and xor-16 fold the warp's
    // 4 ck-subgroups; lanes 0..7 then hold the warp partial for cols 0..7.
    #pragma unroll
    for (int o = 8; o <= 16; o <<= 1) {
        ax += __shfl_xor_sync(0xffffffffu, ax, o);
        ay += __shfl_xor_sync(0xffffffffu, ay, o);
        az += __shfl_xor_sync(0xffffffffu, az, o);
        aw += __shfl_xor_sync(0xffffffffu, aw, o);
    }
    if (lane < 8) swacc[wid][lane] = make_float4(ax, ay, az, aw);
    __syncthreads();

    // warp 0 folds the 8 per-warp partials: lane = j*8+col, j = 0..3
    if (wid == 0) {
        const int c2 = lane & 7;
        const int j  = lane >> 3;                 // 0..3
        float4 s0 = swacc[j][c2];
        float4 s1 = swacc[j + 4][c2];
        float bx = s0.x + s1.x, by = s0.y + s1.y;
        float bz = s0.z + s1.z, bw = s0.w + s1.w;
        #pragma unroll
        for (int o = 8; o <= 16; o <<= 1) {
            bx += __shfl_xor_sync(0xffffffffu, bx, o);
            by += __shfl_xor_sync(0xffffffffu, by, o);
            bz += __shfl_xor_sync(0xffffffffu, bz, o);
            bw += __shfl_xor_sync(0xffffffffu, bw, o);
        }
        if (lane < 8) {
            float4 r = make_float4(bx * inv_l, by * inv_l, bz * inv_l, bw * inv_l);
            ((float4*)(ctx_out + b * HID))[y * 8 + lane] = r;
        }
    }
}

extern "C" void kernel_launch(void* const* d_in, const int* in_sizes, int n_in,
                              void* d_out, int out_size)
{
    const float* dec = (const float*)d_in[0];
    const float* enc = (const float*)d_in[1];
    if (n_in >= 2 && in_sizes[0] > in_sizes[1]) {  // defensive: dec is the small one
        const float* t = dec; dec = enc; enc = t;
    }

    float* out       = (float*)d_out;
    float* prob_out  = out;                       // (B, S)
    float* ctx_out   = out + (size_t)BATCH * SEQ; // (B, H)

    dim3 g1(BATCH, NSPLIT);
    attn_pass1<<<g1, 256>>>(dec, enc, prob_out);
    dim3 g2(BATCH, FIN_Y);
    attn_finish<<<g2, 256>>>(prob_out, ctx_out);
}